// round 6
// baseline (speedup 1.0000x reference)
#include <cuda_runtime.h>
#include <cstdint>

#define T_STEPS 2048
#define BATCH 16
#define DIM 1024
#define NCTA 128
#define STEP_ELEMS (BATCH * DIM)                  // 16384
#define OUTS_ELEMS ((size_t)T_STEPS * STEP_ELEMS) // 33554432

// Per-k-group producer counters. cnt[g] counts arrivals from CTAs [32g,32g+32).
// Reset by init_kernel every launch/replay.
__device__ unsigned int g_cnt[4];

__device__ __forceinline__ float my_tanh(float x) {
    float ax = fabsf(x);
    float e  = __expf(2.0f * ax);
    float r  = 1.0f - 2.0f / (e + 1.0f);
    return copysignf(r, x);
}
__device__ __forceinline__ float my_sigmoid(float x) {
    return 1.0f / (1.0f + __expf(-x));
}

__device__ __forceinline__ void cp_async16(uint32_t smem_addr, const void* gptr) {
    asm volatile("cp.async.cg.shared.global [%0], [%1], 16;\n"
                 :: "r"(smem_addr), "l"(gptr) : "memory");
}
__device__ __forceinline__ void cp_commit() {
    asm volatile("cp.async.commit_group;\n" ::: "memory");
}
#define CP_WAIT(n) asm volatile("cp.async.wait_group %0;\n" :: "n"(n) : "memory")

__device__ __forceinline__ void arrive_release(unsigned* p) {
    asm volatile("red.add.release.gpu.u32 [%0], %1;" :: "l"(p), "r"(1u) : "memory");
}
__device__ __forceinline__ unsigned ld_acquire(unsigned* p) {
    unsigned v;
    asm volatile("ld.acquire.gpu.u32 %0, [%1];" : "=r"(v) : "l"(p) : "memory");
    return v;
}
__device__ __forceinline__ void st_relaxed_gpu(float* p, float v) {
    asm volatile("st.relaxed.gpu.global.f32 [%0], %1;" :: "l"(p), "f"(v) : "memory");
}

// ---------------------------------------------------------------------------
// Init: h0 -> hbuf slot 0; reset the 4 group counters.
// ---------------------------------------------------------------------------
__global__ void init_kernel(const float* __restrict__ h0, float* __restrict__ hbuf) {
    int i = blockIdx.x * blockDim.x + threadIdx.x;
    if (i < STEP_ELEMS) hbuf[i] = h0[i];
    if (i < 4) g_cnt[i] = 0u;
}

// ---------------------------------------------------------------------------
// GEMM: C[m,n] = sum_k A[m,k]*B[n,k] + bias[n]. (R4, ~88% fp32 ceiling)
// ---------------------------------------------------------------------------
__global__ void __launch_bounds__(256, 2)
gemm_kernel(const float* __restrict__ A, const float* __restrict__ Bw,
            const float* __restrict__ bias, float* __restrict__ C) {
    __shared__ float As[2][8][128];
    __shared__ float Bs[2][8][128];

    const int tid = threadIdx.x;
    const int m0 = blockIdx.x * 128;
    const int n0 = blockIdx.y * 128;
    const int lr = tid >> 1;
    const int lc = (tid & 1) * 4;
    const int tx = tid & 15;
    const int ty = tid >> 4;

    const float* Ab = A  + (size_t)(m0 + lr) * DIM + lc;
    const float* Bb = Bw + (size_t)(n0 + lr) * DIM + lc;

    float acc[8][8];
#pragma unroll
    for (int i = 0; i < 8; i++)
#pragma unroll
        for (int j = 0; j < 8; j++) acc[i][j] = 0.0f;

    {
        float4 a4 = *(const float4*)Ab;
        float4 b4 = *(const float4*)Bb;
        As[0][lc + 0][lr] = a4.x; As[0][lc + 1][lr] = a4.y;
        As[0][lc + 2][lr] = a4.z; As[0][lc + 3][lr] = a4.w;
        Bs[0][lc + 0][lr] = b4.x; Bs[0][lc + 1][lr] = b4.y;
        Bs[0][lc + 2][lr] = b4.z; Bs[0][lc + 3][lr] = b4.w;
    }
    __syncthreads();

#pragma unroll 1
    for (int kt = 0; kt < 128; kt++) {
        const int cur = kt & 1;
        float4 na, nb;
        if (kt < 127) {
            na = *(const float4*)(Ab + (kt + 1) * 8);
            nb = *(const float4*)(Bb + (kt + 1) * 8);
        }
#pragma unroll
        for (int kk = 0; kk < 8; kk++) {
            float af[8], bf[8];
            *(float4*)&af[0] = *(const float4*)&As[cur][kk][ty * 8];
            *(float4*)&af[4] = *(const float4*)&As[cur][kk][ty * 8 + 4];
            *(float4*)&bf[0] = *(const float4*)&Bs[cur][kk][tx * 8];
            *(float4*)&bf[4] = *(const float4*)&Bs[cur][kk][tx * 8 + 4];
#pragma unroll
            for (int i = 0; i < 8; i++)
#pragma unroll
                for (int j = 0; j < 8; j++)
                    acc[i][j] = fmaf(af[i], bf[j], acc[i][j]);
        }
        if (kt < 127) {
            const int nxt = cur ^ 1;
            As[nxt][lc + 0][lr] = na.x; As[nxt][lc + 1][lr] = na.y;
            As[nxt][lc + 2][lr] = na.z; As[nxt][lc + 3][lr] = na.w;
            Bs[nxt][lc + 0][lr] = nb.x; Bs[nxt][lc + 1][lr] = nb.y;
            Bs[nxt][lc + 2][lr] = nb.z; Bs[nxt][lc + 3][lr] = nb.w;
        }
        __syncthreads();
    }

#pragma unroll
    for (int i = 0; i < 8; i++) {
        size_t row = (size_t)(m0 + ty * 8 + i) * DIM + n0 + tx * 8;
#pragma unroll
        for (int j = 0; j < 8; j++)
            C[row + j] = acc[i][j] + bias[n0 + tx * 8 + j];
    }
}

// ---------------------------------------------------------------------------
// Persistent recurrence. 128 CTAs x 256 threads; CTA owns 8 e-columns.
// k-dimension split into 4 groups of 256 columns. Group g of h[t] is produced
// by CTAs [32g, 32g+32) — each publishes via red.add.release on g_cnt[g].
// Consumers poll cnt[g] >= t*32 immediately before issuing group-g cp.async,
// interleaved with FMA on already-arrived groups (no full grid barrier).
// Thread (e_loc = tid&7, c8 = tid>>3) computes 1 e-column over k-sets
// {g*256 + c8*8 .. +8} for g = 0..3 (512 FMAs), using h staged in smem.
// ---------------------------------------------------------------------------
__global__ void __launch_bounds__(256, 1)
rnn_kernel(const float* __restrict__ Wh, const float* __restrict__ la,
           float* __restrict__ outs, float* __restrict__ hbuf) {
    extern __shared__ float sm[];
    float* h_sh   = sm;            // 16384 floats (64 KB), row-major [b][k]
    float* part   = sm + 16384;    // 4096 floats  (16 KB)
    float* red_sh = sm + 20480;    // 128 floats

    const int tid   = threadIdx.x;
    const int e_loc = tid & 7;
    const int c8    = tid >> 3;            // 0..31
    const int e     = blockIdx.x * 8 + e_loc;
    const int gid   = blockIdx.x >> 5;     // this CTA's producer group

    const float alpha = __expf(la[0]);

    // Loop-invariant weights: w4[g*2+jj] = Wh[e][g*256 + c8*8 + jj*4 ..+4)
    float4 w4[8];
#pragma unroll
    for (int g = 0; g < 4; g++)
#pragma unroll
        for (int jj = 0; jj < 2; jj++)
            w4[g * 2 + jj] =
                *(const float4*)(Wh + (size_t)e * DIM + g * 256 + c8 * 8 + jj * 4);

    const uint32_t h_u32 = (uint32_t)__cvta_generic_to_shared(h_sh);

    // Reduction / finalize roles (all 256 threads).
    const int out_id  = tid & 127;
    const int halfsel = tid >> 7;          // 0: low (finalize), 1: high
    const int fb = out_id >> 3;
    const int fe = out_id & 7;
    const int eg = blockIdx.x * 8 + fe;

// Poll producers of group G for step t, then issue its cp.async (16 KB:
// per batch b, columns [G*256, G*256+256)). Group float4 unit u in [0,1024):
// b = u>>6, k4 = u&63; slice float4 index = b*256 + G*64 + k4.
#define POLL_ISSUE(G)                                                           \
    do {                                                                        \
        if (tid == 0) {                                                         \
            const unsigned tgt = (unsigned)t * 32u;                             \
            while (ld_acquire(&g_cnt[G]) < tgt) { }                             \
        }                                                                       \
        __syncthreads();                                                        \
        {                                                                       \
            const float4* src = (const float4*)(hbuf + obase);                  \
            _Pragma("unroll")                                                   \
            for (int i = 0; i < 4; i++) {                                       \
                int u = i * 256 + tid;                                          \
                int idx = ((u >> 6) * 256) + (G) * 64 + (u & 63);               \
                cp_async16(h_u32 + (uint32_t)idx * 16u, src + idx);             \
            }                                                                   \
            cp_commit();                                                        \
        }                                                                       \
    } while (0)

// Wait until group G's data is in smem (N groups still pending), then FMA.
#define WAIT_FMA(G, N)                                                          \
    do {                                                                        \
        CP_WAIT(N);                                                             \
        __syncthreads();                                                        \
        _Pragma("unroll")                                                       \
        for (int jj = 0; jj < 2; jj++) {                                        \
            const float4 w = w4[(G) * 2 + jj];                                  \
            const float* hp = h_sh + (G) * 256 + c8 * 8 + jj * 4;               \
            _Pragma("unroll")                                                   \
            for (int b = 0; b < 16; b++) {                                      \
                float4 h4 = *(const float4*)(hp + b * DIM);                     \
                float a = acc[b];                                               \
                a = fmaf(h4.x, w.x, a);                                         \
                a = fmaf(h4.y, w.y, a);                                         \
                a = fmaf(h4.z, w.z, a);                                         \
                a = fmaf(h4.w, w.w, a);                                         \
                acc[b] = a;                                                     \
            }                                                                   \
        }                                                                       \
    } while (0)

    for (int t = 0; t < T_STEPS; t++) {
        const size_t obase = (size_t)t * STEP_ELEMS;

        // Prefetch wx (GEMM output, available since before the kernel started).
        float wx = 0.0f;
        if (halfsel == 0) wx = outs[obase + (size_t)fb * DIM + eg];

        float acc[16];
#pragma unroll
        for (int b = 0; b < 16; b++) acc[b] = 0.0f;

        POLL_ISSUE(0);
        POLL_ISSUE(1);
        WAIT_FMA(0, 1);      // pending {0,1} -> wait g0, compute over it
        POLL_ISSUE(2);
        WAIT_FMA(1, 1);      // pending {1,2} -> wait g1
        POLL_ISSUE(3);
        WAIT_FMA(2, 1);      // pending {2,3} -> wait g2
        WAIT_FMA(3, 0);      // wait g3

        // Publish partials: part[(c8*16 + b)*8 + e_loc]
#pragma unroll
        for (int b = 0; b < 16; b++)
            part[(c8 * 16 + b) * 8 + e_loc] = acc[b];
        __syncthreads();

        // Two-half tree reduction over the 32 c8-chunks.
        float s0 = 0.f, s1 = 0.f, s2 = 0.f, s3 = 0.f;
        {
            const int cbase = halfsel * 16;
#pragma unroll
            for (int c = 0; c < 16; c += 4) {
                s0 += part[((cbase + c + 0) * 16 + fb) * 8 + fe];
                s1 += part[((cbase + c + 1) * 16 + fb) * 8 + fe];
                s2 += part[((cbase + c + 2) * 16 + fb) * 8 + fe];
                s3 += part[((cbase + c + 3) * 16 + fb) * 8 + fe];
            }
        }
        float s = (s0 + s1) + (s2 + s3);
        if (halfsel) red_sh[out_id] = s;
        __syncthreads();

        float hn = 0.0f;
        if (halfsel == 0) {
            float pre  = s + red_sh[out_id] + wx;
            float hold = h_sh[fb * DIM + eg];
            hn = hold + alpha * my_tanh(pre);
            st_relaxed_gpu(&hbuf[(size_t)(t + 1) * STEP_ELEMS + (size_t)fb * DIM + eg], hn);
        }
        __syncthreads();   // all h-slice stores issued before arrival

        if (tid == 0) arrive_release(&g_cnt[gid]);

        // Off the critical path: silu + outs store overlap peers' polls.
        if (halfsel == 0) {
            float ot = hn * hn * my_sigmoid(hn);
            outs[obase + (size_t)fb * DIM + eg] = ot;
        }
    }
#undef POLL_ISSUE
#undef WAIT_FMA
}

// ---------------------------------------------------------------------------
// kernel_launch
//   inputs: x[T,B,D], h0[B,D], W_x[D,D], W_h[D,D], b[D], log_alpha[1]
//   output: [ outs (T*B*D) | h ((T+1)*B*D) ] float32
//   outs doubles as Wx_all scratch: gemm writes Wx there, rnn reads wx[t,b,e]
//   and overwrites the same element with out[t,b,e].
// ---------------------------------------------------------------------------
extern "C" void kernel_launch(void* const* d_in, const int* in_sizes, int n_in,
                              void* d_out, int out_size) {
    const float* x    = (const float*)d_in[0];
    const float* h0   = (const float*)d_in[1];
    const float* Wx   = (const float*)d_in[2];
    const float* Wh   = (const float*)d_in[3];
    const float* bias = (const float*)d_in[4];
    const float* la   = (const float*)d_in[5];

    float* outs = (float*)d_out;
    float* hbuf = outs + OUTS_ELEMS;

    const int smem_bytes = (16384 + 4096 + 128) * sizeof(float);
    cudaFuncSetAttribute(rnn_kernel, cudaFuncAttributeMaxDynamicSharedMemorySize,
                         smem_bytes);

    init_kernel<<<32, 512>>>(h0, hbuf);

    dim3 gg(32768 / 128, DIM / 128);
    gemm_kernel<<<gg, 256>>>(x, Wx, bias, outs);

    rnn_kernel<<<NCTA, 256, smem_bytes>>>(Wh, la, outs, hbuf);
}

// round 7
// speedup vs baseline: 1.1900x; 1.1900x over previous
#include <cuda_runtime.h>
#include <cstdint>

#define T_STEPS 2048
#define BATCH 16
#define DIM 1024
#define NCTA 128
#define STEP_ELEMS (BATCH * DIM)                  // 16384
#define OUTS_ELEMS ((size_t)T_STEPS * STEP_ELEMS) // 33554432

// Grid-barrier counter (monotonic). Reset by init_kernel every launch/replay.
__device__ unsigned int g_cnt0;

__device__ __forceinline__ float my_tanh(float x) {
    float ax = fabsf(x);
    float e  = __expf(2.0f * ax);
    float r  = 1.0f - 2.0f / (e + 1.0f);
    return copysignf(r, x);
}
__device__ __forceinline__ float my_sigmoid(float x) {
    return 1.0f / (1.0f + __expf(-x));
}

__device__ __forceinline__ void cp_async16(uint32_t smem_addr, const void* gptr) {
    asm volatile("cp.async.cg.shared.global [%0], [%1], 16;\n"
                 :: "r"(smem_addr), "l"(gptr) : "memory");
}
__device__ __forceinline__ void cp_commit() {
    asm volatile("cp.async.commit_group;\n" ::: "memory");
}
#define CP_WAIT(n) asm volatile("cp.async.wait_group %0;\n" :: "n"(n) : "memory")

__device__ __forceinline__ void arrive_release(unsigned* p) {
    asm volatile("red.add.release.gpu.u32 [%0], %1;" :: "l"(p), "r"(1u) : "memory");
}
__device__ __forceinline__ unsigned ld_acquire(unsigned* p) {
    unsigned v;
    asm volatile("ld.acquire.gpu.u32 %0, [%1];" : "=r"(v) : "l"(p) : "memory");
    return v;
}
__device__ __forceinline__ void st_relaxed_gpu(float* p, float v) {
    asm volatile("st.relaxed.gpu.global.f32 [%0], %1;" :: "l"(p), "f"(v) : "memory");
}

// ---------------------------------------------------------------------------
// Init: h0 -> hbuf slot 0; reset barrier counter.
// ---------------------------------------------------------------------------
__global__ void init_kernel(const float* __restrict__ h0, float* __restrict__ hbuf) {
    int i = blockIdx.x * blockDim.x + threadIdx.x;
    if (i < STEP_ELEMS) hbuf[i] = h0[i];
    if (i == 0) g_cnt0 = 0u;
}

// ---------------------------------------------------------------------------
// Fused persistent kernel. 128 CTAs x 256 threads; CTA owns 8 e-columns.
// Per step t:
//   - RNN: h[t] broadcast via 4 batch-quarter cp.async groups pipelined into
//     FMA (R4 structure, W_h slice register-resident, bank-rotated).
//   - finalize h[t+1] slice using wx[t] from a smem ring, publish, arrive.
//   - GEMM tail: compute wx[t+1] = x[t+1] @ W_x[8 cols]^T + b from an x tile
//     prefetched 2 steps ahead (cp.async) — fills the barrier-skew window.
// ---------------------------------------------------------------------------
__global__ void __launch_bounds__(256, 1)
fused_kernel(const float* __restrict__ x,  const float* __restrict__ Wx,
             const float* __restrict__ Wh, const float* __restrict__ bias,
             const float* __restrict__ la, float* __restrict__ outs,
             float* __restrict__ hbuf) {
    extern __shared__ float sm[];
    float* h_sh   = sm;            // 16384 floats (64 KB)
    float* part   = sm + 16384;    // 4096 floats  (16 KB)
    float* red_sh = sm + 20480;    // 128 floats
    float* wxr    = sm + 20608;    // 4 x 128 floats (wx ring)
    float* x_sh   = sm + 21120;    // 2 x 16384 floats (128 KB x tiles)

    const int tid   = threadIdx.x;
    const int e_loc = tid & 7;
    const int c8    = tid >> 3;            // 0..31
    const int k0    = c8 * 32;
    const int e     = blockIdx.x * 8 + e_loc;
    const int rot   = c8 & 7;

    const float alpha = __expf(la[0]);

    // Register-resident weight slices, bank-rotated (R4 scheme).
    float4 w4h[8], w4x[8];
    int joff[8];
    {
        const float4* wph = reinterpret_cast<const float4*>(Wh + (size_t)e * DIM + k0);
        const float4* wpx = reinterpret_cast<const float4*>(Wx + (size_t)e * DIM + k0);
#pragma unroll
        for (int jj = 0; jj < 8; jj++) {
            int j = (jj + rot) & 7;
            w4h[jj]  = wph[j];
            w4x[jj]  = wpx[j];
            joff[jj] = 4 * j;
        }
    }

    const uint32_t h_u32 = (uint32_t)__cvta_generic_to_shared(h_sh);
    const uint32_t x_u32 = (uint32_t)__cvta_generic_to_shared(x_sh);

    // Reduction / finalize roles (all 256 threads; out covered by tid<128).
    const int out_id  = tid & 127;
    const int halfsel = tid >> 7;
    const int fb = out_id >> 3;
    const int fe = out_id & 7;
    const int eg = blockIdx.x * 8 + fe;
    const float bias_eg = bias[eg];

// Issue one 16KB x tile (step xt) into x buffer bufp (0/1). One commit group.
#define ISSUE_X(xt, bufp)                                                       \
    do {                                                                        \
        const float4* xs = (const float4*)(x + (size_t)(xt) * STEP_ELEMS);      \
        uint32_t xb = x_u32 + (uint32_t)(bufp) * 65536u;                        \
        _Pragma("unroll")                                                       \
        for (int i = 0; i < 16; i++) {                                          \
            int idx = i * 256 + tid;                                            \
            cp_async16(xb + (uint32_t)idx * 16u, xs + idx);                     \
        }                                                                       \
        cp_commit();                                                            \
    } while (0)

// RNN batch-quarter: wait group G's h data (N groups pending after), FMA.
#define RNN_GROUP(G, N)                                                         \
    do {                                                                        \
        CP_WAIT(N);                                                             \
        __syncthreads();                                                        \
        _Pragma("unroll")                                                       \
        for (int jj = 0; jj < 8; jj++) {                                        \
            const float4 w = w4h[jj];                                           \
            const int off = k0 + joff[jj];                                      \
            _Pragma("unroll")                                                   \
            for (int bb = 0; bb < 4; bb++) {                                    \
                const int b = (G) * 4 + bb;                                     \
                float4 h4 = *(const float4*)(h_sh + b * DIM + off);             \
                float a = accH[b];                                              \
                a = fmaf(h4.x, w.x, a);                                         \
                a = fmaf(h4.y, w.y, a);                                         \
                a = fmaf(h4.z, w.z, a);                                         \
                a = fmaf(h4.w, w.w, a);                                         \
                accH[b] = a;                                                    \
            }                                                                   \
        }                                                                       \
    } while (0)

// GEMM over a full x tile in buffer bufp -> accX[16].
#define GEMM_TILE(bufp)                                                         \
    do {                                                                        \
        const float* xb = x_sh + (bufp) * 16384;                                \
        _Pragma("unroll")                                                       \
        for (int jj = 0; jj < 8; jj++) {                                        \
            const float4 w = w4x[jj];                                           \
            const int off = k0 + joff[jj];                                      \
            _Pragma("unroll")                                                   \
            for (int b = 0; b < 16; b++) {                                      \
                float4 x4 = *(const float4*)(xb + b * DIM + off);               \
                float a = accX[b];                                              \
                a = fmaf(x4.x, w.x, a);                                         \
                a = fmaf(x4.y, w.y, a);                                         \
                a = fmaf(x4.z, w.z, a);                                         \
                a = fmaf(x4.w, w.w, a);                                         \
                accX[b] = a;                                                    \
            }                                                                   \
        }                                                                       \
    } while (0)

// Publish partials, 2-half reduce. Result (tid<128): rsum + red_sh[out_id].
#define REDUCE2H(ACC, rsum)                                                     \
    do {                                                                        \
        _Pragma("unroll")                                                       \
        for (int b = 0; b < 16; b++)                                            \
            part[(c8 * 16 + b) * 8 + e_loc] = ACC[b];                           \
        __syncthreads();                                                        \
        float s0 = 0.f, s1 = 0.f, s2 = 0.f, s3 = 0.f;                           \
        const int cbase = halfsel * 16;                                         \
        _Pragma("unroll")                                                       \
        for (int c = 0; c < 16; c += 4) {                                       \
            s0 += part[((cbase + c + 0) * 16 + fb) * 8 + fe];                   \
            s1 += part[((cbase + c + 1) * 16 + fb) * 8 + fe];                   \
            s2 += part[((cbase + c + 2) * 16 + fb) * 8 + fe];                   \
            s3 += part[((cbase + c + 3) * 16 + fb) * 8 + fe];                   \
        }                                                                       \
        rsum = (s0 + s1) + (s2 + s3);                                           \
        if (halfsel) red_sh[out_id] = rsum;                                     \
        __syncthreads();                                                        \
    } while (0)

    // ---- Prologue: x[0]->buf0, x[1]->buf1; compute wx[0] into ring slot 0.
    ISSUE_X(0, 0);
    ISSUE_X(1, 1);
    CP_WAIT(1);            // x[0] resident
    __syncthreads();
    {
        float accX[16];
#pragma unroll
        for (int b = 0; b < 16; b++) accX[b] = 0.0f;
        GEMM_TILE(0);
        float s;
        REDUCE2H(accX, s);
        if (halfsel == 0)
            wxr[0 * 128 + out_id] = s + red_sh[out_id] + bias_eg;
        __syncthreads();
    }

    // ---- Main loop.
#pragma unroll 1
    for (int t = 0; t < T_STEPS; t++) {
        const size_t obase = (size_t)t * STEP_ELEMS;

        // All-thread acquire-poll: h[t] fully published (t=0 from init).
        if (t > 0) {
            const unsigned tgt = (unsigned)t * NCTA;
            while (ld_acquire(&g_cnt0) < tgt) { }
        }

        // Issue h[t] as 4 batch-quarter groups (16 KB each).
        {
            const float4* src = (const float4*)(hbuf + obase);
#pragma unroll
            for (int g = 0; g < 4; g++) {
#pragma unroll
                for (int i = 0; i < 4; i++) {
                    int idx = g * 1024 + i * 256 + tid;
                    cp_async16(h_u32 + (uint32_t)idx * 16u, src + idx);
                }
                cp_commit();
            }
        }
        // Prefetch x tile 2 steps ahead (clamped; keeps group counts uniform).
        {
            int xt = (t + 2 <= T_STEPS - 1) ? (t + 2) : (T_STEPS - 1);
            ISSUE_X(xt, t & 1);
        }

        float accH[16];
#pragma unroll
        for (int b = 0; b < 16; b++) accH[b] = 0.0f;

        RNN_GROUP(0, 4);   // pending: h1,h2,h3,x
        RNN_GROUP(1, 3);
        RNN_GROUP(2, 2);
        RNN_GROUP(3, 1);   // pending: x

        float hn = 0.0f;
        {
            float s;
            REDUCE2H(accH, s);
            if (halfsel == 0) {
                float pre  = s + red_sh[out_id] + wxr[(t & 3) * 128 + out_id];
                float hold = h_sh[fb * DIM + eg];
                hn = hold + alpha * my_tanh(pre);
                st_relaxed_gpu(&hbuf[(size_t)(t + 1) * STEP_ELEMS
                                     + (size_t)fb * DIM + eg], hn);
            }
        }

        // Ensure this step's x tile (t+1 consumer data from last step is long
        // resident; this wait leaves only x[t+2] pending) and order the h
        // stores of all threads before the arrival.
        CP_WAIT(1);
        __syncthreads();

        if (tid == 0) arrive_release(&g_cnt0);

        // Off-critical-path: silu output store overlaps peers' polls.
        if (halfsel == 0) {
            float ot = hn * hn * my_sigmoid(hn);
            outs[obase + (size_t)fb * DIM + eg] = ot;
        }

        // GEMM tail: wx[t+1] from x buffer (t+1)&1, into ring slot (t+1)&3.
        if (t < T_STEPS - 1) {
            float accX[16];
#pragma unroll
            for (int b = 0; b < 16; b++) accX[b] = 0.0f;
            GEMM_TILE((t + 1) & 1);
            float s;
            REDUCE2H(accX, s);
            if (halfsel == 0)
                wxr[((t + 1) & 3) * 128 + out_id] = s + red_sh[out_id] + bias_eg;
        }
    }
#undef ISSUE_X
#undef RNN_GROUP
#undef GEMM_TILE
#undef REDUCE2H
}

// ---------------------------------------------------------------------------
// kernel_launch
//   inputs: x[T,B,D], h0[B,D], W_x[D,D], W_h[D,D], b[D], log_alpha[1]
//   output: [ outs (T*B*D) | h ((T+1)*B*D) ] float32
// ---------------------------------------------------------------------------
extern "C" void kernel_launch(void* const* d_in, const int* in_sizes, int n_in,
                              void* d_out, int out_size) {
    const float* x    = (const float*)d_in[0];
    const float* h0   = (const float*)d_in[1];
    const float* Wx   = (const float*)d_in[2];
    const float* Wh   = (const float*)d_in[3];
    const float* bias = (const float*)d_in[4];
    const float* la   = (const float*)d_in[5];

    float* outs = (float*)d_out;
    float* hbuf = outs + OUTS_ELEMS;

    const int smem_bytes = (16384 + 4096 + 128 + 512 + 32768) * sizeof(float);
    cudaFuncSetAttribute(fused_kernel, cudaFuncAttributeMaxDynamicSharedMemorySize,
                         smem_bytes);

    init_kernel<<<32, 512>>>(h0, hbuf);
    fused_kernel<<<NCTA, 256, smem_bytes>>>(x, Wx, Wh, bias, la, outs, hbuf);
}